// round 4
// baseline (speedup 1.0000x reference)
#include <cuda_runtime.h>

#define BB 4
#define LL 128
#define DD 256
#define TWO_D 512

// Gram scratch: [b][type][r][k], types: 0=0.5*Q.V^T(+mask), 1=0.5*V.V^T,
//                                        2=0.5*Q.Q^T(+mask), 3=0.5*V.Q^T
__device__ float g_gram[BB * 4 * LL * LL];

// ---------------------------------------------------------------------------
// Kernel 1: Gram matrices. grid (16, B): x = type*4 + rowquarter. 256 threads.
// Each block computes G[type][r0..r0+31][0..127] for one batch.
// ---------------------------------------------------------------------------
__global__ __launch_bounds__(256) void gram_kernel(
    const float* __restrict__ Q, const float* __restrict__ V,
    const int* __restrict__ mask)
{
    int b    = blockIdx.y;
    int type = blockIdx.x >> 2;
    int rq   = blockIdx.x & 3;
    const float* A  = ((type & 1) ? V : Q) + (size_t)b * LL * DD; // 0:Q 1:V 2:Q 3:V
    const float* Bm = ((type < 2) ? V : Q) + (size_t)b * LL * DD; // 0:V 1:V 2:Q 3:Q
    int r0 = rq * 32;

    __shared__ float sA[32 * 65];
    __shared__ float sB[128 * 65];

    float acc[4][4] = {};
    int t = threadIdx.x;

    for (int dc = 0; dc < DD; dc += 64) {
        // sB: 128 rows x 64 cols = 8192 elements -> 32 iterations of 256 threads
        #pragma unroll
        for (int u = 0; u < 32; u++) {
            int idx = t + u * 256;               // 0..8191
            int r = idx >> 6, d = idx & 63;
            sB[r * 65 + d] = Bm[r * DD + dc + d];
        }
        // sA: 32 rows x 64 cols = 2048 elements -> 8 iterations
        #pragma unroll
        for (int u = 0; u < 8; u++) {
            int idx = t + u * 256;               // 0..2047
            int r = idx >> 6, d = idx & 63;
            sA[r * 65 + d] = A[(r0 + r) * DD + dc + d];
        }
        __syncthreads();

        int rg = t >> 5;     // 0..7
        int kg = t & 31;     // 0..31
        const float* sAr = sA + rg * 4 * 65;
        const float* sBr = sB + kg * 4 * 65;
        #pragma unroll 8
        for (int d = 0; d < 64; d++) {
            float av[4], bv[4];
            #pragma unroll
            for (int a = 0; a < 4; a++) av[a] = sAr[a * 65 + d];
            #pragma unroll
            for (int c = 0; c < 4; c++) bv[c] = sBr[c * 65 + d];
            #pragma unroll
            for (int a = 0; a < 4; a++)
                #pragma unroll
                for (int c = 0; c < 4; c++)
                    acc[a][c] = fmaf(av[a], bv[c], acc[a][c]);
        }
        __syncthreads();
    }

    int rg = t >> 5, kg = t & 31;
    float* G = g_gram + (size_t)(b * 4 + type) * LL * LL;
    bool doMask = (type == 0) || (type == 2);
    #pragma unroll
    for (int a = 0; a < 4; a++) {
        #pragma unroll
        for (int c = 0; c < 4; c++) {
            int k = kg * 4 + c;
            float val = 0.5f * acc[a][c];
            if (doMask && mask[b * LL + k] == 0) val = -1e30f;
            G[(r0 + rg * 4 + a) * LL + k] = val;
        }
    }
}

// ---------------------------------------------------------------------------
// Kernel 2: attention + GEMM + LayerNorm.
// grid (2 j-tiles, 128 i, 4 b), 256 threads, dynamic smem.
// ---------------------------------------------------------------------------
#define SP_STRIDE 132
#define OFF_P    0
#define OFF_PQ   (64 * SP_STRIDE)          // 8448
#define OFF_T    (2 * 64 * SP_STRIDE)      // 16896
#define OFF_G1   (OFF_T + 128 * 64)        // 25088
#define OFF_G1Q  (OFF_G1 + 128)            // 25216
#define OFF_W    (OFF_G1Q + 128)           // 25344
#define OFF_BI   (OFF_W + 512)             // 25856
#define OFF_S1   (OFF_BI + 512)            // 26368
#define OFF_S2   (OFF_S1 + 64)             // 26432
#define OFF_MU   (OFF_S2 + 64)             // 26496
#define OFF_RS   (OFF_MU + 64)             // 26560
#define SMEM_FLOATS (OFF_RS + 64)          // 26624
#define SMEM_BYTES  (SMEM_FLOATS * 4)      // 106496

__global__ __launch_bounds__(256, 2) void attn_kernel(
    const float* __restrict__ Q, const float* __restrict__ V,
    const int* __restrict__ mask, const float* __restrict__ nw,
    const float* __restrict__ nb, float* __restrict__ out)
{
    int jt = blockIdx.x, i = blockIdx.y, b = blockIdx.z;
    int t  = threadIdx.x;
    int j0b = jt * 64;
    float* outBase = out + (((size_t)(b * LL + i)) * LL + j0b) * TWO_D;

    // Row mask on i: whole 64x512 region is zero.
    if (mask[b * LL + i] == 0) {
        float4 z = make_float4(0.f, 0.f, 0.f, 0.f);
        float4* o4 = (float4*)outBase;
        #pragma unroll 4
        for (int u = t; u < 64 * TWO_D / 4; u += 256) o4[u] = z;
        return;
    }

    extern __shared__ float sm[];
    float* sP   = sm + OFF_P;
    float* sPq  = sm + OFF_PQ;
    float* sT   = sm + OFF_T;
    float* sG1  = sm + OFF_G1;
    float* sG1q = sm + OFF_G1Q;
    float* sW   = sm + OFF_W;
    float* sBi  = sm + OFF_BI;
    float* sS1  = sm + OFF_S1;
    float* sS2  = sm + OFF_S2;
    float* sMu  = sm + OFF_MU;
    float* sRs  = sm + OFF_RS;

    const float* G   = g_gram + (size_t)b * 4 * LL * LL;
    const float* G2  = G + 1 * LL * LL;
    const float* G2q = G + 3 * LL * LL;

    if (t < 128) {
        sG1[t]  = G[i * LL + t];                 // masked 0.5*q_i . v_k
        sG1q[t] = G[2 * LL * LL + i * LL + t];   // masked 0.5*q_i . q_k
    }
    for (int u = t; u < 512; u += 256) { sW[u] = nw[u]; sBi[u] = nb[u]; }
    if (t < 64) { sS1[t] = 0.f; sS2[t] = 0.f; }
    __syncthreads();

    // ---- Phase A: dual softmax per j row -> P, Pq in smem ----
    int warp = t >> 5, lane = t & 31;
    for (int jj = warp; jj < 64; jj += 8) {
        int j = j0b + jj;
        {
            const float* r = G2 + j * LL;
            float s0 = sG1[lane]      + r[lane];
            float s1 = sG1[lane + 32] + r[lane + 32];
            float s2 = sG1[lane + 64] + r[lane + 64];
            float s3 = sG1[lane + 96] + r[lane + 96];
            float m = fmaxf(fmaxf(s0, s1), fmaxf(s2, s3));
            #pragma unroll
            for (int o = 16; o; o >>= 1) m = fmaxf(m, __shfl_xor_sync(0xffffffffu, m, o));
            float e0 = __expf(s0 - m), e1 = __expf(s1 - m);
            float e2 = __expf(s2 - m), e3 = __expf(s3 - m);
            float su = e0 + e1 + e2 + e3;
            #pragma unroll
            for (int o = 16; o; o >>= 1) su += __shfl_xor_sync(0xffffffffu, su, o);
            float inv = 1.0f / su;
            float* pr = sP + jj * SP_STRIDE;
            pr[lane] = e0 * inv; pr[lane + 32] = e1 * inv;
            pr[lane + 64] = e2 * inv; pr[lane + 96] = e3 * inv;
        }
        {
            const float* r = G2q + j * LL;
            float s0 = sG1q[lane]      + r[lane];
            float s1 = sG1q[lane + 32] + r[lane + 32];
            float s2 = sG1q[lane + 64] + r[lane + 64];
            float s3 = sG1q[lane + 96] + r[lane + 96];
            float m = fmaxf(fmaxf(s0, s1), fmaxf(s2, s3));
            #pragma unroll
            for (int o = 16; o; o >>= 1) m = fmaxf(m, __shfl_xor_sync(0xffffffffu, m, o));
            float e0 = __expf(s0 - m), e1 = __expf(s1 - m);
            float e2 = __expf(s2 - m), e3 = __expf(s3 - m);
            float su = e0 + e1 + e2 + e3;
            #pragma unroll
            for (int o = 16; o; o >>= 1) su += __shfl_xor_sync(0xffffffffu, su, o);
            float inv = 1.0f / su;
            float* pr = sPq + jj * SP_STRIDE;
            pr[lane] = e0 * inv; pr[lane + 32] = e1 * inv;
            pr[lane + 64] = e2 * inv; pr[lane + 96] = e3 * inv;
        }
    }
    __syncthreads();

    // ---- Phase B: out[j, d] = P @ V  /  Pq @ Q, d-tiles of 64 ----
    int jg = t >> 4;   // 0..15 -> j microtile base jg*4
    int dg = t & 15;   // 0..15 -> d microtile base dg*4
    const float* QB = Q + (size_t)b * LL * DD;
    const float* VB = V + (size_t)b * LL * DD;

    #pragma unroll 1
    for (int tile = 0; tile < 8; tile++) {
        int qside = tile >> 2;
        const float* src = qside ? QB : VB;
        int dbase = (tile & 3) * 64;
        #pragma unroll
        for (int u = 0; u < 8; u++) {
            int idx = t + u * 256;               // float4 index 0..2047
            int k = idx >> 4, c4 = idx & 15;
            *(float4*)&sT[k * 64 + c4 * 4] =
                *(const float4*)&src[k * DD + dbase + c4 * 4];
        }
        __syncthreads();

        const float* P   = qside ? sPq : sP;
        const float* Pr0 = P + jg * 4 * SP_STRIDE;
        float acc[4][4] = {};
        #pragma unroll 4
        for (int k = 0; k < 128; k += 4) {
            float pk[4][4];   // [a][kk]
            float tk[4][4];   // [kk][c]
            #pragma unroll
            for (int a = 0; a < 4; a++)
                *(float4*)pk[a] = *(const float4*)&Pr0[a * SP_STRIDE + k];
            #pragma unroll
            for (int kk = 0; kk < 4; kk++)
                *(float4*)tk[kk] = *(const float4*)&sT[(k + kk) * 64 + dg * 4];
            #pragma unroll
            for (int a = 0; a < 4; a++)
                #pragma unroll
                for (int kk = 0; kk < 4; kk++)
                    #pragma unroll
                    for (int c = 0; c < 4; c++)
                        acc[a][c] = fmaf(pk[a][kk], tk[kk][c], acc[a][c]);
        }

        int dglob = qside * 256 + dbase + dg * 4;
        #pragma unroll
        for (int a = 0; a < 4; a++) {
            int j = jg * 4 + a;
            float4 r = make_float4(acc[a][0], acc[a][1], acc[a][2], acc[a][3]);
            *(float4*)&outBase[(size_t)j * TWO_D + dglob] = r;
            atomicAdd(&sS1[j], r.x + r.y + r.z + r.w);
            atomicAdd(&sS2[j], r.x * r.x + r.y * r.y + r.z * r.z + r.w * r.w);
        }
        __syncthreads();
    }

    // ---- Phase C: LayerNorm in place (own region is L2-hot) ----
    if (t < 64) {
        float mu  = sS1[t] * (1.0f / 512.0f);
        float var = sS2[t] * (1.0f / 512.0f) - mu * mu;
        sMu[t] = mu;
        sRs[t] = rsqrtf(var + 1e-5f);
    }
    __syncthreads();

    int jr = t >> 2, part = t & 3;
    float mu = sMu[jr], rs = sRs[jr];
    float* orow = outBase + (size_t)jr * TWO_D;
    #pragma unroll 8
    for (int it = 0; it < 32; it++) {
        int idx4 = it * 4 + part;       // 0..127
        int d = idx4 * 4;
        float4 x = *(float4*)&orow[d];
        x.x = (x.x - mu) * rs * sW[d + 0] + sBi[d + 0];
        x.y = (x.y - mu) * rs * sW[d + 1] + sBi[d + 1];
        x.z = (x.z - mu) * rs * sW[d + 2] + sBi[d + 2];
        x.w = (x.w - mu) * rs * sW[d + 3] + sBi[d + 3];
        *(float4*)&orow[d] = x;
    }
    // mask[b,i] == 1 guaranteed here, so no final mask multiply needed.
}

// ---------------------------------------------------------------------------
extern "C" void kernel_launch(void* const* d_in, const int* in_sizes, int n_in,
                              void* d_out, int out_size)
{
    const float* q    = (const float*)d_in[0];
    const float* v    = (const float*)d_in[1];
    const int*   mask = (const int*)d_in[2];
    const float* nw   = (const float*)d_in[3];
    const float* nb   = (const float*)d_in[4];
    float* out = (float*)d_out;

    gram_kernel<<<dim3(16, BB), 256>>>(q, v, mask);

    cudaFuncSetAttribute(attn_kernel,
                         cudaFuncAttributeMaxDynamicSharedMemorySize, SMEM_BYTES);
    attn_kernel<<<dim3(2, LL, BB), 256, SMEM_BYTES>>>(q, v, mask, nw, nb, out);
}